// round 6
// baseline (speedup 1.0000x reference)
#include <cuda_runtime.h>
#include <cuda_bf16.h>

// Lp_Conv2D_BT: out[b,o,i,j] = max_{k<4} | w[o,k] - x_pad[b, c_k, i+di_k-1, j+dj_k-1] | + bias[o]
// edge padding (clamp), stride 1.
// x:(32,64,64,64) f32; weights:(128,4) f32; bias:(128,1,1) f32; conn_idx:(128,4) i32.
// out:(32,128,64,64) f32.

namespace {
constexpr int HW   = 64;
constexpr int CIN  = 64;
constexpr int COUT = 128;
constexpr int CONN = 4;
}

__device__ __forceinline__ unsigned long long add_f32x2(unsigned long long a,
                                                        unsigned long long b) {
    unsigned long long r;
    asm("add.rn.f32x2 %0, %1, %2;" : "=l"(r) : "l"(a), "l"(b));
    return r;
}

__device__ __forceinline__ unsigned long long bcast_f32x2(float v) {
    unsigned long long r;
    asm("mov.b64 %0, {%1, %1};" : "=l"(r) : "f"(v));
    return r;
}

__device__ __forceinline__ void unpack_f32x2(unsigned long long v, float& lo, float& hi) {
    asm("mov.b64 {%0, %1}, %2;" : "=f"(lo), "=f"(hi) : "l"(v));
}

__global__ __launch_bounds__(256) void lp_conv_bt_kernel(
    const float* __restrict__ x,
    const float* __restrict__ weights,
    const float* __restrict__ bias,
    const int*   __restrict__ conn_idx,
    float*       __restrict__ out)
{
    const int blk = blockIdx.x;          // blk = b*COUT + o
    const int o   = blk & (COUT - 1);
    const int b   = blk >> 7;
    const int t   = threadIdx.x;

    // Per-output-channel connection parameters (uniform across the block).
    const float* px[CONN];
    int dr[CONN], dc[CONN];
    unsigned long long nw2[CONN];        // packed {-w, -w}
#pragma unroll
    for (int k = 0; k < CONN; ++k) {
        const int idx = __ldg(conn_idx + o * CONN + k);   // [0, 576)
        const int c   = idx / 9;
        const int rem = idx - c * 9;
        const int di  = rem / 3;
        dr[k] = di - 1;                   // {-1,0,1}
        dc[k] = (rem - di * 3) - 1;       // {-1,0,1}, uniform per block
        px[k] = x + ((size_t)b * CIN + c) * (HW * HW);
        nw2[k] = bcast_f32x2(-__ldg(weights + o * CONN + k));
    }
    const float bs = __ldg(bias + o);

    // 16 lanes cover one row (contiguous float4 per lane); a warp spans 2
    // adjacent rows -> each LDG.128 covers 4x128B lines (wavefront minimum).
    const int lane16 = t & 15;
    const int r0     = t >> 4;           // 0..15
    float4* po = reinterpret_cast<float4*>(out + (size_t)blk * (HW * HW));

#pragma unroll
    for (int rb = 0; rb < 4; ++rb) {
        const int row = r0 + rb * 16;

        // Row clamp only at extreme row-blocks (dr in {-1,0,1}).
        const ulonglong2* p[CONN];
#pragma unroll
        for (int k = 0; k < CONN; ++k) {
            int rr = row + dr[k];
            if (rb == 0)      rr = max(rr, 0);
            else if (rb == 3) rr = min(rr, HW - 1);
            p[k] = reinterpret_cast<const ulonglong2*>(px[k] + rr * HW) + lane16;
        }

        // Issue the 4 independent LDG.128 before any dependent op.
        ulonglong2 v[CONN];
#pragma unroll
        for (int k = 0; k < CONN; ++k) v[k] = *p[k];

        float m0 = 0.f, m1 = 0.f, m2 = 0.f, m3 = 0.f;   // |.| >= 0

#pragma unroll
        for (int k = 0; k < CONN; ++k) {
            // Packed d = g - w for the 4 loaded columns (2 instrs instead of 4).
            const unsigned long long dlo = add_f32x2(v[k].x, nw2[k]);
            const unsigned long long dhi = add_f32x2(v[k].y, nw2[k]);
            float d0, d1, d2, d3;
            unpack_f32x2(dlo, d0, d1);
            unpack_f32x2(dhi, d2, d3);

            // Apply the block-uniform column shift to d (|g-w| == |w-g|).
            float a0, a1, a2, a3;
            if (dc[k] == 0) {
                a0 = d0; a1 = d1; a2 = d2; a3 = d3;
            } else if (dc[k] > 0) {
                // cols j0+1..j0+4 ; j0+4 = next lane's d0 (col 64 -> clamp 63 = d3)
                float e = __shfl_down_sync(0xffffffffu, d0, 1, 16);
                if (lane16 == 15) e = d3;
                a0 = d1; a1 = d2; a2 = d3; a3 = e;
            } else {
                // cols j0-1..j0+2 ; j0-1 = prev lane's d3 (col -1 -> clamp 0 = d0)
                float e = __shfl_up_sync(0xffffffffu, d3, 1, 16);
                if (lane16 == 0) e = d0;
                a0 = e; a1 = d0; a2 = d1; a3 = d2;
            }

            m0 = fmaxf(m0, fabsf(a0));
            m1 = fmaxf(m1, fabsf(a1));
            m2 = fmaxf(m2, fabsf(a2));
            m3 = fmaxf(m3, fabsf(a3));
        }

        // Streaming store: contiguous float4 per lane (4 lines/warp, minimal).
        __stcs(po + row * 16 + lane16,
               make_float4(m0 + bs, m1 + bs, m2 + bs, m3 + bs));
    }
}

extern "C" void kernel_launch(void* const* d_in, const int* in_sizes, int n_in,
                              void* d_out, int out_size) {
    const float* x       = (const float*)d_in[0];
    const float* weights = (const float*)d_in[1];
    const float* bias    = (const float*)d_in[2];
    const int*   conn    = (const int*)d_in[3];
    float*       out     = (float*)d_out;

    const int B = in_sizes[0] / (CIN * HW * HW);   // 32
    lp_conv_bt_kernel<<<B * COUT, 256>>>(x, weights, bias, conn, out);
}

// round 7
// speedup vs baseline: 1.0875x; 1.0875x over previous
#include <cuda_runtime.h>
#include <cuda_bf16.h>

// Lp_Conv2D_BT: out[b,o,i,j] = max_{k<4} | w[o,k] - x_pad[b, c_k, i+di_k-1, j+dj_k-1] | + bias[o]
// edge padding (clamp), stride 1.
// x:(32,64,64,64) f32; weights:(128,4) f32; bias:(128,1,1) f32; conn_idx:(128,4) i32.
// out:(32,128,64,64) f32.

namespace {
constexpr int HW   = 64;
constexpr int CIN  = 64;
constexpr int COUT = 128;
constexpr int CONN = 4;
}

__global__ __launch_bounds__(256) void lp_conv_bt_kernel(
    const float* __restrict__ x,
    const float* __restrict__ weights,
    const float* __restrict__ bias,
    const int*   __restrict__ conn_idx,
    float*       __restrict__ out)
{
    const int blk = blockIdx.x;          // blk = b*COUT + o
    const int o   = blk & (COUT - 1);
    const int b   = blk >> 7;
    const int t   = threadIdx.x;

    const int lane16 = t & 15;
    const int r0     = t >> 4;           // 0..15

    const float* xb = x + (size_t)b * CIN * (HW * HW);

    // Per-output-channel connection parameters (uniform across the block).
    // Base pointer per k points at row (r0 + dr), lane offset folded in.
    // Row-blocks 1,2 use immediate offsets (+16*HW, +32*HW); edge row-blocks
    // 0,3 use the precomputed clamp adjustments a0/a3 (elements).
    const float* bp[CONN];
    int a0[CONN], a3[CONN], dc[CONN];
    float w[CONN];
#pragma unroll
    for (int k = 0; k < CONN; ++k) {
        const int idx = __ldg(conn_idx + o * CONN + k);   // [0, 576)
        const int c   = idx / 9;
        const int rem = idx - c * 9;
        const int di  = rem / 3;
        const int drk = di - 1;                            // {-1,0,1}
        dc[k] = (rem - di * 3) - 1;                        // {-1,0,1}
        w[k]  = __ldg(weights + o * CONN + k);
        bp[k] = xb + c * (HW * HW) + (r0 + drk) * HW + lane16 * 4;
        a0[k] = ((r0 + drk) < 0) ? HW : 0;                 // only r0==0, dr==-1
        a3[k] = ((r0 + 48 + drk) > HW - 1) ? -HW : 0;      // only r0==15, dr==+1
    }
    const float bs = __ldg(bias + o);

    float4* po = reinterpret_cast<float4*>(out + (size_t)blk * (HW * HW));

    auto body = [&](const float4 v0, const float4 v1, const float4 v2,
                    const float4 v3, int row) {
        float m0 = 0.f, m1 = 0.f, m2 = 0.f, m3 = 0.f;     // |.| >= 0
        const float4 vk[CONN] = {v0, v1, v2, v3};
#pragma unroll
        for (int k = 0; k < CONN; ++k) {
            const float4 vv = vk[k];
            float g0, g1, g2, g3;
            if (dc[k] == 0) {
                g0 = vv.x; g1 = vv.y; g2 = vv.z; g3 = vv.w;
            } else if (dc[k] > 0) {
                // cols j0+1..j0+4 ; j0+4 = next lane's vv.x (col 64 -> clamp 63 = vv.w)
                float e = __shfl_down_sync(0xffffffffu, vv.x, 1, 16);
                if (lane16 == 15) e = vv.w;
                g0 = vv.y; g1 = vv.z; g2 = vv.w; g3 = e;
            } else {
                // cols j0-1..j0+2 ; j0-1 = prev lane's vv.w (col -1 -> clamp 0 = vv.x)
                float e = __shfl_up_sync(0xffffffffu, vv.w, 1, 16);
                if (lane16 == 0) e = vv.x;
                g0 = e; g1 = vv.x; g2 = vv.y; g3 = vv.z;
            }
            const float wk = w[k];
            m0 = fmaxf(m0, fabsf(wk - g0));
            m1 = fmaxf(m1, fabsf(wk - g1));
            m2 = fmaxf(m2, fabsf(wk - g2));
            m3 = fmaxf(m3, fabsf(wk - g3));
        }
        __stcs(po + row * 16 + lane16,
               make_float4(m0 + bs, m1 + bs, m2 + bs, m3 + bs));
    };

    auto ld = [](const float* p) {
        return __ldg(reinterpret_cast<const float4*>(p));
    };

    // rb0 (lower-edge clamp via a0)
    {
        const float4 v0 = ld(bp[0] + a0[0]);
        const float4 v1 = ld(bp[1] + a0[1]);
        const float4 v2 = ld(bp[2] + a0[2]);
        const float4 v3 = ld(bp[3] + a0[3]);
        body(v0, v1, v2, v3, r0);
    }
    // rb1, rb2 (no clamp; immediate offsets)
    {
        const float4 v0 = ld(bp[0] + 16 * HW);
        const float4 v1 = ld(bp[1] + 16 * HW);
        const float4 v2 = ld(bp[2] + 16 * HW);
        const float4 v3 = ld(bp[3] + 16 * HW);
        body(v0, v1, v2, v3, r0 + 16);
    }
    {
        const float4 v0 = ld(bp[0] + 32 * HW);
        const float4 v1 = ld(bp[1] + 32 * HW);
        const float4 v2 = ld(bp[2] + 32 * HW);
        const float4 v3 = ld(bp[3] + 32 * HW);
        body(v0, v1, v2, v3, r0 + 32);
    }
    // rb3 (upper-edge clamp via a3)
    {
        const float4 v0 = ld(bp[0] + 48 * HW + a3[0]);
        const float4 v1 = ld(bp[1] + 48 * HW + a3[1]);
        const float4 v2 = ld(bp[2] + 48 * HW + a3[2]);
        const float4 v3 = ld(bp[3] + 48 * HW + a3[3]);
        body(v0, v1, v2, v3, r0 + 48);
    }
}

extern "C" void kernel_launch(void* const* d_in, const int* in_sizes, int n_in,
                              void* d_out, int out_size) {
    const float* x       = (const float*)d_in[0];
    const float* weights = (const float*)d_in[1];
    const float* bias    = (const float*)d_in[2];
    const int*   conn    = (const int*)d_in[3];
    float*       out     = (float*)d_out;

    const int B = in_sizes[0] / (CIN * HW * HW);   // 32
    lp_conv_bt_kernel<<<B * COUT, 256>>>(x, weights, bias, conn, out);
}